// round 16
// baseline (speedup 1.0000x reference)
#include <cuda_runtime.h>
#include <cuda_bf16.h>
#include <cstdint>
#include <cstddef>
#include <math.h>

// Problem constants
#define BATCH 768
#define UNITS 256
#define DHID  1024
#define GROUPS 8
#define J1N   96              // BATCH / GROUPS
#define BATCH2 1536           // 2 * BATCH (key rows then query rows)
#define W_ELEMS 150994944ll   // 768*768*256
#define MASK_ELEMS (BATCH * UNITS)

// ---------------- device scratch (no allocations allowed) ----------------
__device__ float g_H[BATCH2 * DHID];          // hidden activations (leaky), 6.3MB
__device__ float g_part[4 * BATCH2 * UNITS];  // split-K partials for GEMM2
__device__ float g_Ek [BATCH * UNITS];        // exp(key*t)
__device__ float g_iEk[BATCH * UNITS];        // 1/exp(key*t)
__device__ float g_Eq [BATCH * UNITS];        // exp(query*t)
__device__ float g_iEq[BATCH * UNITS];        // 1/exp(query*t)
__device__ int   g_mask_mode;                 // 0=f32, 1=bf16, 2=i32, 3=u8

__device__ __forceinline__ bool mask_at(const void* m, int mode, int idx) {
    switch (mode) {
        case 0:  return ((const float*)m)[idx] != 0.0f;
        case 1:  return ((const unsigned short*)m)[idx] != 0;
        case 2:  return ((const int*)m)[idx] != 0;
        default: return ((const unsigned char*)m)[idx] != 0;
    }
}

// ---------------- GEMM1: H[1536,1024] = leaky(X2[1536,256] @ W1 + b1) ----
// (R2/R12 version — measured good. Rows 0..767 = x, 768..1535 = masked x.)
#define BM 64
#define BN 64
#define BK 16

__global__ __launch_bounds__(256) void k_gemm1(
    const float* __restrict__ x, const void* __restrict__ mask,
    const float* __restrict__ W1, const float* __restrict__ b1)
{
    __shared__ float As[BK][BM];
    __shared__ float Bs[BK][BN];
    const int tid = threadIdx.x;

    // inline mask dtype detection (uniform result, cheap barriers).
    // Also serves the softmax tail writer later in the stream.
    {
        unsigned int v = ((const unsigned int*)mask)[tid];
        unsigned int h0 = v & 0xFFFFu, h1 = v >> 16;
        int m_f32 = __syncthreads_and((v == 0u) || (v == 0x3F800000u));
        int m_bf  = __syncthreads_and((h0 == 0u || h0 == 0x3F80u) &&
                                      (h1 == 0u || h1 == 0x3F80u));
        int m_i32 = __syncthreads_and(v <= 1u);
        g_mask_mode = m_f32 ? 0 : (m_bf ? 1 : (m_i32 ? 2 : 3));
    }
    const int mmode = g_mask_mode;

    const int bn = blockIdx.x;            // 0..15
    const int bm = blockIdx.y;            // 0..23
    const int tx = tid & 15, ty = tid >> 4;
    const int row0 = bm * BM, col0 = bn * BN;

    const int am  = tid >> 2;             // 0..63 (row in tile)
    const int akq = (tid & 3) * 4;        // 0,4,8,12 (k quad)
    const int bk_ = tid >> 4;             // 0..15 (k in tile)
    const int bnq = (tid & 15) * 4;       // n quad

    float acc[4][4];
#pragma unroll
    for (int r = 0; r < 4; r++)
#pragma unroll
        for (int c = 0; c < 4; c++) acc[r][c] = 0.f;

    for (int k0 = 0; k0 < UNITS; k0 += BK) {
        int gr = row0 + am;
        float4 av;
        if (gr < BATCH) {
            av = *(const float4*)(x + gr * UNITS + k0 + akq);
        } else {
            int r = gr - BATCH;
            int base = r * UNITS + k0 + akq;
            av = *(const float4*)(x + base);
            if (mask_at(mask, mmode, base + 0)) av.x = 0.f;
            if (mask_at(mask, mmode, base + 1)) av.y = 0.f;
            if (mask_at(mask, mmode, base + 2)) av.z = 0.f;
            if (mask_at(mask, mmode, base + 3)) av.w = 0.f;
        }
        As[akq + 0][am] = av.x; As[akq + 1][am] = av.y;
        As[akq + 2][am] = av.z; As[akq + 3][am] = av.w;
        *(float4*)&Bs[bk_][bnq] =
            *(const float4*)(W1 + (size_t)(k0 + bk_) * DHID + col0 + bnq);
        __syncthreads();
#pragma unroll
        for (int kk = 0; kk < BK; kk++) {
            float4 a4 = *(const float4*)&As[kk][ty * 4];
            float4 b4 = *(const float4*)&Bs[kk][tx * 4];
            float a[4] = {a4.x, a4.y, a4.z, a4.w};
            float b[4] = {b4.x, b4.y, b4.z, b4.w};
#pragma unroll
            for (int r = 0; r < 4; r++)
#pragma unroll
                for (int c = 0; c < 4; c++) acc[r][c] += a[r] * b[c];
        }
        __syncthreads();
    }
    float4 bb = *(const float4*)(b1 + col0 + tx * 4);
    float bias[4] = {bb.x, bb.y, bb.z, bb.w};
#pragma unroll
    for (int r = 0; r < 4; r++) {
        int gm = row0 + ty * 4 + r;
        float4 o;
        float v0 = acc[r][0] + bias[0]; o.x = v0 > 0.f ? v0 : 0.01f * v0;
        float v1 = acc[r][1] + bias[1]; o.y = v1 > 0.f ? v1 : 0.01f * v1;
        float v2 = acc[r][2] + bias[2]; o.z = v2 > 0.f ? v2 : 0.01f * v2;
        float v3 = acc[r][3] + bias[3]; o.w = v3 > 0.f ? v3 : 0.01f * v3;
        *(float4*)(g_H + (size_t)gm * DHID + col0 + tx * 4) = o;
    }
}

// ---------------- GEMM2 (split-K=4): part[z] = H[:,z*256:(z+1)*256] @ W2 --
// (R2/R12 version — measured good.)
__global__ __launch_bounds__(256) void k_gemm2(const float* __restrict__ W2)
{
    __shared__ float As[BK][BM];
    __shared__ float Bs[BK][BN];
    const int bn = blockIdx.x;            // 0..3
    const int bm = blockIdx.y;            // 0..23
    const int kz = blockIdx.z;            // 0..3
    const int tid = threadIdx.x;
    const int tx = tid & 15, ty = tid >> 4;
    const int row0 = bm * BM, col0 = bn * BN;
    const int kbeg = kz * 256;

    const int am  = tid >> 2;
    const int akq = (tid & 3) * 4;
    const int bk_ = tid >> 4;
    const int bnq = (tid & 15) * 4;

    float acc[4][4];
#pragma unroll
    for (int r = 0; r < 4; r++)
#pragma unroll
        for (int c = 0; c < 4; c++) acc[r][c] = 0.f;

    for (int k0 = kbeg; k0 < kbeg + 256; k0 += BK) {
        int gr = row0 + am;
        float4 av = *(const float4*)(g_H + (size_t)gr * DHID + k0 + akq);
        As[akq + 0][am] = av.x; As[akq + 1][am] = av.y;
        As[akq + 2][am] = av.z; As[akq + 3][am] = av.w;
        *(float4*)&Bs[bk_][bnq] =
            *(const float4*)(W2 + (size_t)(k0 + bk_) * UNITS + col0 + bnq);
        __syncthreads();
#pragma unroll
        for (int kk = 0; kk < BK; kk++) {
            float4 a4 = *(const float4*)&As[kk][ty * 4];
            float4 b4 = *(const float4*)&Bs[kk][tx * 4];
            float a[4] = {a4.x, a4.y, a4.z, a4.w};
            float b[4] = {b4.x, b4.y, b4.z, b4.w};
#pragma unroll
            for (int r = 0; r < 4; r++)
#pragma unroll
                for (int c = 0; c < 4; c++) acc[r][c] += a[r] * b[c];
        }
        __syncthreads();
    }
    float* outp = g_part + (size_t)kz * BATCH2 * UNITS;
#pragma unroll
    for (int r = 0; r < 4; r++) {
        int gm = row0 + ty * 4 + r;
        float4 o = make_float4(acc[r][0], acc[r][1], acc[r][2], acc[r][3]);
        *(float4*)(outp + (size_t)gm * UNITS + col0 + tx * 4) = o;
    }
}

// ---------------- reduce split-K, add b2, build exp tables (float4) ------
__global__ void k_reduce_exp(const float* __restrict__ b2,
                             const float* __restrict__ temp)
{
    int q = blockIdx.x * blockDim.x + threadIdx.x;   // quad index
    if (q >= BATCH2 * UNITS / 4) return;
    int idx = q * 4;
    int row = idx >> 8;
    int uq = idx & 255;
    const int S = BATCH2 * UNITS;
    float4 p0 = *(const float4*)(g_part + idx);
    float4 p1 = *(const float4*)(g_part + idx + S);
    float4 p2 = *(const float4*)(g_part + idx + 2 * S);
    float4 p3 = *(const float4*)(g_part + idx + 3 * S);
    float4 bb = *(const float4*)(b2 + uq);
    float4 tt = *(const float4*)(temp + uq);
    float4 e, ie;
    e.x = expf((p0.x + p1.x + p2.x + p3.x + bb.x) * tt.x); ie.x = 1.0f / e.x;
    e.y = expf((p0.y + p1.y + p2.y + p3.y + bb.y) * tt.y); ie.y = 1.0f / e.y;
    e.z = expf((p0.z + p1.z + p2.z + p3.z + bb.z) * tt.z); ie.z = 1.0f / e.z;
    e.w = expf((p0.w + p1.w + p2.w + p3.w + bb.w) * tt.w); ie.w = 1.0f / e.w;
    if (row < BATCH) {
        *(float4*)(g_Ek  + idx) = e;
        *(float4*)(g_iEk + idx) = ie;
    } else {
        int o = idx - BATCH * UNITS;
        *(float4*)(g_Eq  + o) = e;
        *(float4*)(g_iEq + o) = ie;
    }
}

// ---------------- fused softmax + write (the 604MB kernel) ----------------
// At the HBM write wall (~5 TB/s measured across layouts) — math untouched.
// exp(-|k-q|t) = min(Ek*invEq, Eq*invEk).  Block owns ONE j2 and ALL 256 u;
// thread keeps Ek/invEk for its (j2,u) over all 96 j1 in registers.
// The 8 ib==0 blocks additionally append the tuple's mask tail (tiny vs the
// 604MB stream), eliminating two extra kernel launches.
#define NBI 37
__global__ __launch_bounds__(256, 1) void k_softmax_write(
    float* __restrict__ w, const void* __restrict__ mask, long long extra)
{
    const int j2 = blockIdx.x;                 // 0..7
    const int ib = blockIdx.y;                 // 0..NBI-1
    const int lane = threadIdx.x & 31;
    const int uc = threadIdx.x >> 5;           // 0..7 (u chunk)
    const int u = uc * 32 + lane;

    float ek[J1N], iek[J1N];
    const float* Ekp  = g_Ek  + j2 * UNITS + u;
    const float* iEkp = g_iEk + j2 * UNITS + u;
#pragma unroll
    for (int j1 = 0; j1 < J1N; j1++) {
        ek[j1]  = Ekp [j1 * (GROUPS * UNITS)];
        iek[j1] = iEkp[j1 * (GROUPS * UNITS)];
    }

    const int i0 = (ib * BATCH) / NBI;
    const int i1 = ((ib + 1) * BATCH) / NBI;
    for (int i = i0; i < i1; i++) {
        float eq  = g_Eq [i * UNITS + u];
        float ieq = g_iEq[i * UNITS + u];
        float s = 0.f;
#pragma unroll
        for (int j1 = 0; j1 < J1N; j1++)
            s += fminf(ek[j1] * ieq, iek[j1] * eq);
        const bool diag = ((i & 7) == j2);     // uniform across block
        const int jd = i >> 3;
        if (diag) s -= fminf(ek[jd] * ieq, iek[jd] * eq);
        float r = 1.0f / (8.0f * s);
        float f1 = ieq * r, f2 = eq * r;
        float* base = w + ((size_t)i * BATCH + j2) * UNITS + u;
#pragma unroll
        for (int j1 = 0; j1 < J1N; j1++)
            __stcs(base + (size_t)j1 * (GROUPS * UNITS),
                   fminf(ek[j1] * f1, iek[j1] * f2));
        if (diag) __stcs(base + (size_t)jd * (GROUPS * UNITS), 0.0f);
    }

    // mask tail of the tuple output (g_mask_mode set by k_gemm1 upstream)
    if (extra > 0 && ib == 0) {
        const int mmode = g_mask_mode;
        float* tail = w + W_ELEMS;
        long long per = (extra + GROUPS - 1) / GROUPS;
        long long t0 = (long long)j2 * per;
        long long t1 = t0 + per; if (t1 > extra) t1 = extra;
        for (long long t = t0 + threadIdx.x; t < t1; t += 256) {
            float v = 0.0f;
            if (t < MASK_ELEMS)
                v = mask_at(mask, mmode, (int)t) ? 1.0f : 0.0f;
            __stcs(tail + t, v);
        }
    }
}

// ---------------- launch ----------------
extern "C" void kernel_launch(void* const* d_in, const int* in_sizes, int n_in,
                              void* d_out, int out_size)
{
    const float* x    = (const float*)d_in[0];
    const void*  mask = d_in[1];
    const float* W1   = (const float*)d_in[2];
    const float* b1   = (const float*)d_in[3];
    const float* W2   = (const float*)d_in[4];
    const float* b2   = (const float*)d_in[5];
    const float* temp = (const float*)d_in[6];
    float* out = (float*)d_out;

    // H = leaky(X2 @ W1 + b1)   (mask-mode detection inlined)
    k_gemm1<<<dim3(DHID / BN, BATCH2 / BM), 256>>>(x, mask, W1, b1);

    // partials = H @ W2 (split-K)
    k_gemm2<<<dim3(UNITS / BN, BATCH2 / BM, 4), 256>>>(W2);

    // key/query + exp tables
    k_reduce_exp<<<(BATCH2 * UNITS / 4 + 255) / 256, 256>>>(b2, temp);

    // big fused softmax + write (+ mask tail folded in): 8 j2 x NBI i-blocks
    long long extra = (long long)out_size - W_ELEMS;
    if (extra < 0) extra = 0;
    k_softmax_write<<<dim3(GROUPS, NBI), 256>>>(out, mask, extra);
}

// round 17
// speedup vs baseline: 1.0553x; 1.0553x over previous
#include <cuda_runtime.h>
#include <cuda_bf16.h>
#include <cstdint>
#include <cstddef>
#include <math.h>

// Problem constants
#define BATCH 768
#define UNITS 256
#define DHID  1024
#define GROUPS 8
#define J1N   96              // BATCH / GROUPS
#define BATCH2 1536           // 2 * BATCH (key rows then query rows)
#define W_ELEMS 150994944ll   // 768*768*256

// ---------------- device scratch (no allocations allowed) ----------------
__device__ float g_H[BATCH2 * DHID];          // hidden activations (leaky), 6.3MB
__device__ float g_part[4 * BATCH2 * UNITS];  // split-K partials for GEMM2
__device__ float g_Ek [BATCH * UNITS];        // exp(key*t)
__device__ float g_iEk[BATCH * UNITS];        // 1/exp(key*t)
__device__ float g_Eq [BATCH * UNITS];        // exp(query*t)
__device__ float g_iEq[BATCH * UNITS];        // 1/exp(query*t)
__device__ int   g_mask_mode;                 // 0=f32, 1=bf16, 2=i32, 3=u8

__device__ __forceinline__ bool mask_at(const void* m, int mode, int idx) {
    switch (mode) {
        case 0:  return ((const float*)m)[idx] != 0.0f;
        case 1:  return ((const unsigned short*)m)[idx] != 0;
        case 2:  return ((const int*)m)[idx] != 0;
        default: return ((const unsigned char*)m)[idx] != 0;
    }
}

// ---------------- GEMM1: H[1536,1024] = leaky(X2[1536,256] @ W1 + b1) ----
// (R2/R12 version — measured good. Rows 0..767 = x, 768..1535 = masked x.)
#define BM 64
#define BN 64
#define BK 16

__global__ __launch_bounds__(256) void k_gemm1(
    const float* __restrict__ x, const void* __restrict__ mask,
    const float* __restrict__ W1, const float* __restrict__ b1)
{
    __shared__ float As[BK][BM];
    __shared__ float Bs[BK][BN];
    const int tid = threadIdx.x;

    // inline mask dtype detection (uniform result, cheap barriers).
    // Also serves k_mask_tail later in the stream.
    {
        unsigned int v = ((const unsigned int*)mask)[tid];
        unsigned int h0 = v & 0xFFFFu, h1 = v >> 16;
        int m_f32 = __syncthreads_and((v == 0u) || (v == 0x3F800000u));
        int m_bf  = __syncthreads_and((h0 == 0u || h0 == 0x3F80u) &&
                                      (h1 == 0u || h1 == 0x3F80u));
        int m_i32 = __syncthreads_and(v <= 1u);
        g_mask_mode = m_f32 ? 0 : (m_bf ? 1 : (m_i32 ? 2 : 3));
    }
    const int mmode = g_mask_mode;

    const int bn = blockIdx.x;            // 0..15
    const int bm = blockIdx.y;            // 0..23
    const int tx = tid & 15, ty = tid >> 4;
    const int row0 = bm * BM, col0 = bn * BN;

    const int am  = tid >> 2;             // 0..63 (row in tile)
    const int akq = (tid & 3) * 4;        // 0,4,8,12 (k quad)
    const int bk_ = tid >> 4;             // 0..15 (k in tile)
    const int bnq = (tid & 15) * 4;       // n quad

    float acc[4][4];
#pragma unroll
    for (int r = 0; r < 4; r++)
#pragma unroll
        for (int c = 0; c < 4; c++) acc[r][c] = 0.f;

    for (int k0 = 0; k0 < UNITS; k0 += BK) {
        int gr = row0 + am;
        float4 av;
        if (gr < BATCH) {
            av = *(const float4*)(x + gr * UNITS + k0 + akq);
        } else {
            int r = gr - BATCH;
            int base = r * UNITS + k0 + akq;
            av = *(const float4*)(x + base);
            if (mask_at(mask, mmode, base + 0)) av.x = 0.f;
            if (mask_at(mask, mmode, base + 1)) av.y = 0.f;
            if (mask_at(mask, mmode, base + 2)) av.z = 0.f;
            if (mask_at(mask, mmode, base + 3)) av.w = 0.f;
        }
        As[akq + 0][am] = av.x; As[akq + 1][am] = av.y;
        As[akq + 2][am] = av.z; As[akq + 3][am] = av.w;
        *(float4*)&Bs[bk_][bnq] =
            *(const float4*)(W1 + (size_t)(k0 + bk_) * DHID + col0 + bnq);
        __syncthreads();
#pragma unroll
        for (int kk = 0; kk < BK; kk++) {
            float4 a4 = *(const float4*)&As[kk][ty * 4];
            float4 b4 = *(const float4*)&Bs[kk][tx * 4];
            float a[4] = {a4.x, a4.y, a4.z, a4.w};
            float b[4] = {b4.x, b4.y, b4.z, b4.w};
#pragma unroll
            for (int r = 0; r < 4; r++)
#pragma unroll
                for (int c = 0; c < 4; c++) acc[r][c] += a[r] * b[c];
        }
        __syncthreads();
    }
    float4 bb = *(const float4*)(b1 + col0 + tx * 4);
    float bias[4] = {bb.x, bb.y, bb.z, bb.w};
#pragma unroll
    for (int r = 0; r < 4; r++) {
        int gm = row0 + ty * 4 + r;
        float4 o;
        float v0 = acc[r][0] + bias[0]; o.x = v0 > 0.f ? v0 : 0.01f * v0;
        float v1 = acc[r][1] + bias[1]; o.y = v1 > 0.f ? v1 : 0.01f * v1;
        float v2 = acc[r][2] + bias[2]; o.z = v2 > 0.f ? v2 : 0.01f * v2;
        float v3 = acc[r][3] + bias[3]; o.w = v3 > 0.f ? v3 : 0.01f * v3;
        *(float4*)(g_H + (size_t)gm * DHID + col0 + tx * 4) = o;
    }
}

// ---------------- GEMM2 (split-K=4): part[z] = H[:,z*256:(z+1)*256] @ W2 --
// (R2/R12 version — measured good.)
__global__ __launch_bounds__(256) void k_gemm2(const float* __restrict__ W2)
{
    __shared__ float As[BK][BM];
    __shared__ float Bs[BK][BN];
    const int bn = blockIdx.x;            // 0..3
    const int bm = blockIdx.y;            // 0..23
    const int kz = blockIdx.z;            // 0..3
    const int tid = threadIdx.x;
    const int tx = tid & 15, ty = tid >> 4;
    const int row0 = bm * BM, col0 = bn * BN;
    const int kbeg = kz * 256;

    const int am  = tid >> 2;
    const int akq = (tid & 3) * 4;
    const int bk_ = tid >> 4;
    const int bnq = (tid & 15) * 4;

    float acc[4][4];
#pragma unroll
    for (int r = 0; r < 4; r++)
#pragma unroll
        for (int c = 0; c < 4; c++) acc[r][c] = 0.f;

    for (int k0 = kbeg; k0 < kbeg + 256; k0 += BK) {
        int gr = row0 + am;
        float4 av = *(const float4*)(g_H + (size_t)gr * DHID + k0 + akq);
        As[akq + 0][am] = av.x; As[akq + 1][am] = av.y;
        As[akq + 2][am] = av.z; As[akq + 3][am] = av.w;
        *(float4*)&Bs[bk_][bnq] =
            *(const float4*)(W2 + (size_t)(k0 + bk_) * UNITS + col0 + bnq);
        __syncthreads();
#pragma unroll
        for (int kk = 0; kk < BK; kk++) {
            float4 a4 = *(const float4*)&As[kk][ty * 4];
            float4 b4 = *(const float4*)&Bs[kk][tx * 4];
            float a[4] = {a4.x, a4.y, a4.z, a4.w};
            float b[4] = {b4.x, b4.y, b4.z, b4.w};
#pragma unroll
            for (int r = 0; r < 4; r++)
#pragma unroll
                for (int c = 0; c < 4; c++) acc[r][c] += a[r] * b[c];
        }
        __syncthreads();
    }
    float* outp = g_part + (size_t)kz * BATCH2 * UNITS;
#pragma unroll
    for (int r = 0; r < 4; r++) {
        int gm = row0 + ty * 4 + r;
        float4 o = make_float4(acc[r][0], acc[r][1], acc[r][2], acc[r][3]);
        *(float4*)(outp + (size_t)gm * UNITS + col0 + tx * 4) = o;
    }
}

// ---------------- reduce split-K, add b2, build exp tables (float4) ------
__global__ void k_reduce_exp(const float* __restrict__ b2,
                             const float* __restrict__ temp)
{
    int q = blockIdx.x * blockDim.x + threadIdx.x;   // quad index
    if (q >= BATCH2 * UNITS / 4) return;
    int idx = q * 4;
    int row = idx >> 8;
    int uq = idx & 255;
    const int S = BATCH2 * UNITS;
    float4 p0 = *(const float4*)(g_part + idx);
    float4 p1 = *(const float4*)(g_part + idx + S);
    float4 p2 = *(const float4*)(g_part + idx + 2 * S);
    float4 p3 = *(const float4*)(g_part + idx + 3 * S);
    float4 bb = *(const float4*)(b2 + uq);
    float4 tt = *(const float4*)(temp + uq);
    float4 e, ie;
    e.x = expf((p0.x + p1.x + p2.x + p3.x + bb.x) * tt.x); ie.x = 1.0f / e.x;
    e.y = expf((p0.y + p1.y + p2.y + p3.y + bb.y) * tt.y); ie.y = 1.0f / e.y;
    e.z = expf((p0.z + p1.z + p2.z + p3.z + bb.z) * tt.z); ie.z = 1.0f / e.z;
    e.w = expf((p0.w + p1.w + p2.w + p3.w + bb.w) * tt.w); ie.w = 1.0f / e.w;
    if (row < BATCH) {
        *(float4*)(g_Ek  + idx) = e;
        *(float4*)(g_iEk + idx) = ie;
    } else {
        int o = idx - BATCH * UNITS;
        *(float4*)(g_Eq  + o) = e;
        *(float4*)(g_iEq + o) = ie;
    }
}

// ---------------- fused softmax + write (the 604MB kernel) ----------------
// BYTE-IDENTICAL to the measured 119.6us R12 version — at the HBM write
// wall; R15 proved any code added to this kernel perturbs the hot loop.
// exp(-|k-q|t) = min(Ek*invEq, Eq*invEk).  Block owns ONE j2 and ALL 256 u;
// thread keeps Ek/invEk for its (j2,u) over all 96 j1 in registers.
#define NBI 37
__global__ __launch_bounds__(256, 1) void k_softmax_write(float* __restrict__ w)
{
    const int j2 = blockIdx.x;                 // 0..7
    const int ib = blockIdx.y;                 // 0..NBI-1
    const int lane = threadIdx.x & 31;
    const int uc = threadIdx.x >> 5;           // 0..7 (u chunk)
    const int u = uc * 32 + lane;

    float ek[J1N], iek[J1N];
    const float* Ekp  = g_Ek  + j2 * UNITS + u;
    const float* iEkp = g_iEk + j2 * UNITS + u;
#pragma unroll
    for (int j1 = 0; j1 < J1N; j1++) {
        ek[j1]  = Ekp [j1 * (GROUPS * UNITS)];
        iek[j1] = iEkp[j1 * (GROUPS * UNITS)];
    }

    const int i0 = (ib * BATCH) / NBI;
    const int i1 = ((ib + 1) * BATCH) / NBI;
    for (int i = i0; i < i1; i++) {
        float eq  = g_Eq [i * UNITS + u];
        float ieq = g_iEq[i * UNITS + u];
        float s = 0.f;
#pragma unroll
        for (int j1 = 0; j1 < J1N; j1++)
            s += fminf(ek[j1] * ieq, iek[j1] * eq);
        const bool diag = ((i & 7) == j2);     // uniform across block
        const int jd = i >> 3;
        if (diag) s -= fminf(ek[jd] * ieq, iek[jd] * eq);
        float r = 1.0f / (8.0f * s);
        float f1 = ieq * r, f2 = eq * r;
        float* base = w + ((size_t)i * BATCH + j2) * UNITS + u;
#pragma unroll
        for (int j1 = 0; j1 < J1N; j1++)
            __stcs(base + (size_t)j1 * (GROUPS * UNITS),
                   fminf(ek[j1] * f1, iek[j1] * f2));
        if (diag) __stcs(base + (size_t)jd * (GROUPS * UNITS), 0.0f);
    }
}

// ---------------- optional mask tail of the tuple output -----------------
// g_mask_mode was computed by k_gemm1 at the head of the stream; the old
// standalone k_detect_mask launch (5.2us serial, per R13 ncu) is removed.
__global__ void k_mask_tail(float* __restrict__ out, const void* __restrict__ mask,
                            long long extra)
{
    long long idx = (long long)blockIdx.x * blockDim.x + threadIdx.x;
    if (idx >= extra) return;
    float v = 0.0f;
    if (idx < BATCH * UNITS)
        v = mask_at(mask, g_mask_mode, (int)idx) ? 1.0f : 0.0f;
    out[idx] = v;
}

// ---------------- launch ----------------
extern "C" void kernel_launch(void* const* d_in, const int* in_sizes, int n_in,
                              void* d_out, int out_size)
{
    const float* x    = (const float*)d_in[0];
    const void*  mask = d_in[1];
    const float* W1   = (const float*)d_in[2];
    const float* b1   = (const float*)d_in[3];
    const float* W2   = (const float*)d_in[4];
    const float* b2   = (const float*)d_in[5];
    const float* temp = (const float*)d_in[6];
    float* out = (float*)d_out;

    // H = leaky(X2 @ W1 + b1)   (mask-mode detection inlined)
    k_gemm1<<<dim3(DHID / BN, BATCH2 / BM), 256>>>(x, mask, W1, b1);

    // partials = H @ W2 (split-K)
    k_gemm2<<<dim3(UNITS / BN, BATCH2 / BM, 4), 256>>>(W2);

    // key/query + exp tables
    k_reduce_exp<<<(BATCH2 * UNITS / 4 + 255) / 256, 256>>>(b2, temp);

    // big fused softmax + write: grid = 8 j2 x NBI i-blocks
    k_softmax_write<<<dim3(GROUPS, NBI), 256>>>(out);

    // if output is the whole tuple (w, mask), fill the mask tail
    // (mode already in g_mask_mode from k_gemm1 — no detect launch)
    long long extra = (long long)out_size - W_ELEMS;
    if (extra > 0) {
        int nb = (int)((extra + 255) / 256);
        k_mask_tail<<<nb, 256>>>(out + W_ELEMS, mask, extra);
    }
}